// round 5
// baseline (speedup 1.0000x reference)
#include <cuda_runtime.h>
#include <cuda_bf16.h>
#include <math.h>
#include <stdint.h>

#define B_  8192
#define D_  768
#define GH_ 384
#define E_  8
#define H_  3072

#define OFF_GATE ((size_t)B_ * D_)
#define OFF_EO   (OFF_GATE + (size_t)B_ * E_)

__device__ float g_g[(size_t)B_ * GH_];
__device__ __align__(16) __nv_bfloat16 g_hhi[(size_t)B_ * D_];
__device__ __align__(16) __nv_bfloat16 g_hlo[(size_t)B_ * D_];
__device__ __align__(16) __nv_bfloat16 g_gw1hi[(size_t)GH_ * D_];
__device__ __align__(16) __nv_bfloat16 g_gw1lo[(size_t)GH_ * D_];
__device__ __align__(16) __nv_bfloat16 g_w1hi[(size_t)E_ * H_ * D_];
__device__ __align__(16) __nv_bfloat16 g_w1lo[(size_t)E_ * H_ * D_];
__device__ __align__(16) __nv_bfloat16 g_w2hi[(size_t)E_ * D_ * H_];
__device__ __align__(16) __nv_bfloat16 g_w2lo[(size_t)E_ * D_ * H_];
__device__ __align__(16) __nv_bfloat16 g_hidhi[(size_t)E_ * B_ * H_];
__device__ __align__(16) __nv_bfloat16 g_hidlo[(size_t)E_ * B_ * H_];
__device__ float g_tw[B_ * 2];
__device__ int   g_ti[B_ * 2];

__device__ __forceinline__ uint32_t smem_to_u32(const void* p) {
    uint32_t a;
    asm("{ .reg .u64 t; cvta.to.shared.u64 t, %1; cvt.u32.u64 %0, t; }" : "=r"(a) : "l"(p));
    return a;
}
__device__ __forceinline__ float geluf(float x) {
    return 0.5f * x * (1.f + erff(x * 0.7071067811865475f));
}
__device__ __forceinline__ void splitbf(float v, __nv_bfloat16& h, __nv_bfloat16& l) {
    h = __float2bfloat16(v);
    l = __float2bfloat16(v - __bfloat162float(h));
}
__device__ __forceinline__ uint32_t pack2(__nv_bfloat16 a, __nv_bfloat16 b) {
    return (uint32_t)__bfloat16_as_ushort(a) | ((uint32_t)__bfloat16_as_ushort(b) << 16);
}
__device__ __forceinline__ void cpa16(uint32_t dst, const void* src) {
    asm volatile("cp.async.cg.shared.global [%0], [%1], 16;" :: "r"(dst), "l"(src));
}
#define CP_COMMIT() asm volatile("cp.async.commit_group;" ::: "memory")
#define CP_WAIT1()  asm volatile("cp.async.wait_group 1;" ::: "memory")
#define CP_WAIT0()  asm volatile("cp.async.wait_group 0;" ::: "memory")

#define LDSM4(r, addr)                                                          \
    asm volatile("ldmatrix.sync.aligned.m8n8.x4.shared.b16 {%0,%1,%2,%3}, [%4];"\
                 : "=r"((r)[0]), "=r"((r)[1]), "=r"((r)[2]), "=r"((r)[3])       \
                 : "r"(addr))

#define MMA_BF16(d, a, b0, b1)                                                  \
    asm volatile("mma.sync.aligned.m16n8k16.row.col.f32.bf16.bf16.f32 "         \
                 "{%0,%1,%2,%3}, {%4,%5,%6,%7}, {%8,%9}, {%0,%1,%2,%3};"        \
                 : "+f"((d)[0]), "+f"((d)[1]), "+f"((d)[2]), "+f"((d)[3])       \
                 : "r"((a)[0]), "r"((a)[1]), "r"((a)[2]), "r"((a)[3]),          \
                   "r"(b0), "r"(b1))

// ---------------------------------------------------------------------------
__global__ void ln_kernel(const float* __restrict__ x,
                          const float* __restrict__ gamma,
                          const float* __restrict__ beta) {
    int b = blockIdx.x;
    const float* row = x + (size_t)b * D_;
    float s = 0.f, s2 = 0.f;
    for (int i = threadIdx.x; i < D_; i += blockDim.x) {
        float v = row[i];
        s += v; s2 += v * v;
    }
    __shared__ float red[64];
    for (int o = 16; o; o >>= 1) {
        s  += __shfl_down_sync(0xffffffffu, s,  o);
        s2 += __shfl_down_sync(0xffffffffu, s2, o);
    }
    int wid = threadIdx.x >> 5, lid = threadIdx.x & 31;
    if (lid == 0) { red[wid] = s; red[wid + 32] = s2; }
    __syncthreads();
    int nw = blockDim.x >> 5;
    if (wid == 0) {
        s  = (lid < nw) ? red[lid]      : 0.f;
        s2 = (lid < nw) ? red[lid + 32] : 0.f;
        for (int o = 16; o; o >>= 1) {
            s  += __shfl_down_sync(0xffffffffu, s,  o);
            s2 += __shfl_down_sync(0xffffffffu, s2, o);
        }
        if (lid == 0) { red[0] = s; red[1] = s2; }
    }
    __syncthreads();
    float mu   = red[0] / D_;
    float var  = red[1] / D_ - mu * mu;
    float rstd = rsqrtf(var + 1e-5f);
    for (int i = threadIdx.x; i < D_; i += blockDim.x) {
        float v = (row[i] - mu) * rstd * gamma[i] + beta[i];
        size_t idx = (size_t)b * D_ + i;
        __nv_bfloat16 hi, lo;
        splitbf(v, hi, lo);
        g_hhi[idx] = hi;
        g_hlo[idx] = lo;
    }
}

// ---------------------------------------------------------------------------
__global__ void transpose_split_kernel(const float* __restrict__ src,
                                       __nv_bfloat16* __restrict__ dhi,
                                       __nv_bfloat16* __restrict__ dlo,
                                       int R, int C) {
    __shared__ float t[32][33];
    int e = blockIdx.z;
    int c0 = blockIdx.x * 32, r0 = blockIdx.y * 32;
    const float* s = src + (size_t)e * R * C;
    #pragma unroll
    for (int i = 0; i < 32; i += 8)
        t[threadIdx.y + i][threadIdx.x] =
            s[(size_t)(r0 + threadIdx.y + i) * C + c0 + threadIdx.x];
    __syncthreads();
    size_t ob = (size_t)e * C * R;
    #pragma unroll
    for (int i = 0; i < 32; i += 8) {
        float v = t[threadIdx.x][threadIdx.y + i];
        __nv_bfloat16 hi, lo;
        splitbf(v, hi, lo);
        size_t o = ob + (size_t)(c0 + threadIdx.y + i) * R + r0 + threadIdx.x;
        dhi[o] = hi;
        dlo[o] = lo;
    }
}

// ---------------------------------------------------------------------------
// bf16x3 GEMM: mma.sync m16n8k16 + ldmatrix + cp.async 3-stage pipeline.
// C = op(A[e] @ B[e]^T + bias[e]); A [M,K] hi/lo row-major, B [N,K] hi/lo row-major.
// Tile 128x128x32, 256 threads (8 warps, 2x4 of 64x32 warp tiles).
// The 3 compensation terms are issued TERM-MAJOR so that MMAs hitting the same
// accumulator are 16 independent issues apart (no RAW stalls on the HMMA pipe).
// OUT_MODE: 0 = fp32 +bias, 1 = fp32 gelu, 2 = gelu + bf16 hi/lo split
// ---------------------------------------------------------------------------
#define BKC 32
#define LDAE 40                       // padded row stride (bf16 elems) = 80 bytes
#define REG_BYTES (128 * LDAE * 2)    // 10240
#define STAGE_B (4 * REG_BYTES)       // 40960
#define NSTG 3
#define SMEM_TC (NSTG * STAGE_B)      // 122880

template <int OUT_MODE>
__global__ void __launch_bounds__(256) gemm_bf16x3(
    const __nv_bfloat16* __restrict__ Ahi, const __nv_bfloat16* __restrict__ Alo,
    const __nv_bfloat16* __restrict__ Bhi, const __nv_bfloat16* __restrict__ Blo,
    const float* __restrict__ bias,
    __nv_bfloat16* __restrict__ OutHi, __nv_bfloat16* __restrict__ OutLo,
    float* __restrict__ OutF,
    int Ktot, size_t aStrideE, size_t bStrideE, size_t biasStrideE,
    size_t cStrideE, int ldc, int cColStride)
{
    extern __shared__ char smem[];
    uint32_t sbase = smem_to_u32(smem);
    int tid  = threadIdx.x;
    int warp = tid >> 5, lane = tid & 31;
    int e  = blockIdx.z;
    int bm = blockIdx.y * 128;
    int bn = blockIdx.x * 128;
    int wm = (warp >> 2) * 64;
    int wn = (warp & 3)  * 32;
    int g  = lane >> 2, tg = lane & 3;

    const __nv_bfloat16* pAhi = Ahi + (size_t)e * aStrideE + (size_t)bm * Ktot;
    const __nv_bfloat16* pAlo = Alo + (size_t)e * aStrideE + (size_t)bm * Ktot;
    const __nv_bfloat16* pBhi = Bhi + (size_t)e * bStrideE + (size_t)bn * Ktot;
    const __nv_bfloat16* pBlo = Blo + (size_t)e * bStrideE + (size_t)bn * Ktot;

    int r0c = tid >> 2, cc0 = tid & 3;
    int r1c = r0c + 64;

    int mi = lane >> 3, rr = lane & 7;
    uint32_t a_addr = sbase
        + (uint32_t)(wm + (mi & 1) * 8 + rr) * 80 + (uint32_t)(mi >> 1) * 16;
    uint32_t b_addr = sbase + 2u * REG_BYTES
        + (uint32_t)(wn + (mi >> 1) * 8 + rr) * 80 + (uint32_t)(mi & 1) * 16;

    float acc[4][4][4];
    #pragma unroll
    for (int i = 0; i < 4; i++)
        #pragma unroll
        for (int j = 0; j < 4; j++)
            #pragma unroll
            for (int r = 0; r < 4; r++) acc[i][j][r] = 0.f;

    const int NC = Ktot / BKC;

    auto load_chunk = [&](int c, int st) {
        int k0 = c * BKC;
        uint32_t sb = sbase + (uint32_t)st * STAGE_B;
        uint32_t d0 = sb + (uint32_t)r0c * 80 + (uint32_t)cc0 * 16;
        uint32_t d1 = sb + (uint32_t)r1c * 80 + (uint32_t)cc0 * 16;
        size_t g0 = (size_t)r0c * Ktot + k0 + cc0 * 8;
        size_t g1 = (size_t)r1c * Ktot + k0 + cc0 * 8;
        cpa16(d0,                 pAhi + g0);
        cpa16(d0 + REG_BYTES,     pAlo + g0);
        cpa16(d1,                 pAhi + g1);
        cpa16(d1 + REG_BYTES,     pAlo + g1);
        cpa16(d0 + 2u*REG_BYTES,  pBhi + g0);
        cpa16(d0 + 3u*REG_BYTES,  pBlo + g0);
        cpa16(d1 + 2u*REG_BYTES,  pBhi + g1);
        cpa16(d1 + 3u*REG_BYTES,  pBlo + g1);
        CP_COMMIT();
    };

    load_chunk(0, 0);
    if (NC > 1) load_chunk(1, 1);

    for (int c = 0; c < NC; c++) {
        if (c + 1 < NC) { CP_WAIT1(); } else { CP_WAIT0(); }
        __syncthreads();
        if (c + 2 < NC) load_chunk(c + 2, (c + 2) % NSTG);

        uint32_t stoff = (uint32_t)((c % NSTG) * STAGE_B);
        #pragma unroll
        for (int ks = 0; ks < 2; ks++) {
            uint32_t ah[4][4], al[4][4], bh[2][4], bl[2][4];
            #pragma unroll
            for (int i = 0; i < 4; i++) {
                uint32_t ad = a_addr + stoff + (uint32_t)i * 1280 + (uint32_t)ks * 32;
                LDSM4(ah[i], ad);
                LDSM4(al[i], ad + REG_BYTES);
            }
            #pragma unroll
            for (int jp = 0; jp < 2; jp++) {
                uint32_t bd = b_addr + stoff + (uint32_t)jp * 1280 + (uint32_t)ks * 32;
                LDSM4(bh[jp], bd);
                LDSM4(bl[jp], bd + REG_BYTES);
            }
            // Term-major: 16 independent accumulators between same-acc reuse
            #pragma unroll
            for (int i = 0; i < 4; i++)
                #pragma unroll
                for (int j = 0; j < 4; j++) {
                    int jp = j >> 1, hf = (j & 1) * 2;
                    MMA_BF16(acc[i][j], ah[i], bh[jp][hf], bh[jp][hf + 1]);
                }
            #pragma unroll
            for (int i = 0; i < 4; i++)
                #pragma unroll
                for (int j = 0; j < 4; j++) {
                    int jp = j >> 1, hf = (j & 1) * 2;
                    MMA_BF16(acc[i][j], ah[i], bl[jp][hf], bl[jp][hf + 1]);
                }
            #pragma unroll
            for (int i = 0; i < 4; i++)
                #pragma unroll
                for (int j = 0; j < 4; j++) {
                    int jp = j >> 1, hf = (j & 1) * 2;
                    MMA_BF16(acc[i][j], al[i], bh[jp][hf], bh[jp][hf + 1]);
                }
        }
    }

    const float* bp = bias + (size_t)e * biasStrideE;
    #pragma unroll
    for (int i = 0; i < 4; i++) {
        int r0 = bm + wm + i * 16 + g;
        #pragma unroll
        for (int j = 0; j < 4; j++) {
            int c0 = bn + wn + j * 8 + tg * 2;
            float bi0 = bp[c0], bi1 = bp[c0 + 1];
            float v0 = acc[i][j][0] + bi0, v1 = acc[i][j][1] + bi1;
            float v2 = acc[i][j][2] + bi0, v3 = acc[i][j][3] + bi1;
            size_t rbA = (size_t)e * cStrideE + (size_t)r0 * ldc
                       + (size_t)e * cColStride + c0;
            size_t rbB = rbA + (size_t)8 * ldc;
            if (OUT_MODE == 0) {
                OutF[rbA] = v0; OutF[rbA + 1] = v1;
                OutF[rbB] = v2; OutF[rbB + 1] = v3;
            } else if (OUT_MODE == 1) {
                OutF[rbA] = geluf(v0); OutF[rbA + 1] = geluf(v1);
                OutF[rbB] = geluf(v2); OutF[rbB + 1] = geluf(v3);
            } else {
                v0 = geluf(v0); v1 = geluf(v1); v2 = geluf(v2); v3 = geluf(v3);
                __nv_bfloat16 h0, l0, h1, l1;
                splitbf(v0, h0, l0); splitbf(v1, h1, l1);
                *(uint32_t*)(OutHi + rbA) = pack2(h0, h1);
                *(uint32_t*)(OutLo + rbA) = pack2(l0, l1);
                splitbf(v2, h0, l0); splitbf(v3, h1, l1);
                *(uint32_t*)(OutHi + rbB) = pack2(h0, h1);
                *(uint32_t*)(OutLo + rbB) = pack2(l0, l1);
            }
        }
    }
}

// ---------------------------------------------------------------------------
__global__ void gate_kernel(const float* __restrict__ gw2,
                            const float* __restrict__ gb2,
                            float* __restrict__ dout) {
    int b = blockIdx.x * (blockDim.x >> 5) + (threadIdx.x >> 5);
    if (b >= B_) return;
    int lane = threadIdx.x & 31;
    int e = lane & 7, s = lane >> 3;

    const float* gr = g_g + (size_t)b * GH_;
    float acc = 0.f;
    int k0 = s * (GH_ / 4);
    #pragma unroll 4
    for (int k = k0; k < k0 + GH_ / 4; k++)
        acc = fmaf(gr[k], gw2[k * E_ + e], acc);
    acc += __shfl_xor_sync(0xffffffffu, acc, 8);
    acc += __shfl_xor_sync(0xffffffffu, acc, 16);
    float logit = acc + gb2[e];

    float m = logit;
    for (int o = 4; o; o >>= 1) m = fmaxf(m, __shfl_xor_sync(0xffffffffu, m, o));
    float p = (lane < E_) ? expf(logit - m) : 0.f;
    float ssum = p;
    for (int o = 16; o; o >>= 1) ssum += __shfl_xor_sync(0xffffffffu, ssum, o);
    float prob = p / ssum;
    if (lane < E_) dout[OFF_GATE + (size_t)b * E_ + lane] = prob;

    float v1 = (lane < E_) ? prob : -1.f; int i1 = lane;
    for (int o = 16; o; o >>= 1) {
        float ov = __shfl_xor_sync(0xffffffffu, v1, o);
        int   oi = __shfl_xor_sync(0xffffffffu, i1, o);
        if (ov > v1 || (ov == v1 && oi < i1)) { v1 = ov; i1 = oi; }
    }
    float v2 = (lane < E_ && lane != i1) ? prob : -1.f; int i2 = lane;
    for (int o = 16; o; o >>= 1) {
        float ov = __shfl_xor_sync(0xffffffffu, v2, o);
        int   oi = __shfl_xor_sync(0xffffffffu, i2, o);
        if (ov > v2 || (ov == v2 && oi < i2)) { v2 = ov; i2 = oi; }
    }
    if (lane == 0) {
        float sw = v1 + v2;
        g_tw[b * 2 + 0] = v1 / sw;
        g_tw[b * 2 + 1] = v2 / sw;
        g_ti[b * 2 + 0] = i1;
        g_ti[b * 2 + 1] = i2;
    }
}

// ---------------------------------------------------------------------------
__global__ void combine_kernel(float* __restrict__ dout) {
    size_t i = (size_t)blockIdx.x * blockDim.x + threadIdx.x;
    if (i >= (size_t)B_ * D_) return;
    int b = (int)(i / D_), d = (int)(i % D_);
    int   i0 = g_ti[b * 2], i1 = g_ti[b * 2 + 1];
    float w0 = g_tw[b * 2], w1 = g_tw[b * 2 + 1];
    const float* eo = dout + OFF_EO + (size_t)b * E_ * D_;
    dout[i] = w0 * eo[(size_t)i0 * D_ + d] + w1 * eo[(size_t)i1 * D_ + d];
}

// ---------------------------------------------------------------------------
extern "C" void kernel_launch(void* const* d_in, const int* in_sizes, int n_in,
                              void* d_out, int out_size) {
    const float* x     = (const float*)d_in[0];
    const float* gamma = (const float*)d_in[1];
    const float* beta  = (const float*)d_in[2];
    const float* gw1   = (const float*)d_in[3];
    const float* gb1   = (const float*)d_in[4];
    const float* gw2   = (const float*)d_in[5];
    const float* gb2   = (const float*)d_in[6];
    const float* ew1   = (const float*)d_in[7];
    const float* eb1   = (const float*)d_in[8];
    const float* ew2   = (const float*)d_in[9];
    const float* eb2   = (const float*)d_in[10];
    float* out = (float*)d_out;

    float *pg;
    __nv_bfloat16 *phhi, *phlo, *pgw1hi, *pgw1lo, *pw1hi, *pw1lo, *pw2hi, *pw2lo,
                  *phidhi, *phidlo;
    cudaGetSymbolAddress((void**)&pg,     g_g);
    cudaGetSymbolAddress((void**)&phhi,   g_hhi);
    cudaGetSymbolAddress((void**)&phlo,   g_hlo);
    cudaGetSymbolAddress((void**)&pgw1hi, g_gw1hi);
    cudaGetSymbolAddress((void**)&pgw1lo, g_gw1lo);
    cudaGetSymbolAddress((void**)&pw1hi,  g_w1hi);
    cudaGetSymbolAddress((void**)&pw1lo,  g_w1lo);
    cudaGetSymbolAddress((void**)&pw2hi,  g_w2hi);
    cudaGetSymbolAddress((void**)&pw2lo,  g_w2lo);
    cudaGetSymbolAddress((void**)&phidhi, g_hidhi);
    cudaGetSymbolAddress((void**)&phidlo, g_hidlo);

    cudaFuncSetAttribute(gemm_bf16x3<0>, cudaFuncAttributeMaxDynamicSharedMemorySize, SMEM_TC);
    cudaFuncSetAttribute(gemm_bf16x3<1>, cudaFuncAttributeMaxDynamicSharedMemorySize, SMEM_TC);
    cudaFuncSetAttribute(gemm_bf16x3<2>, cudaFuncAttributeMaxDynamicSharedMemorySize, SMEM_TC);

    // 1. LayerNorm + bf16 split
    ln_kernel<<<B_, 256>>>(x, gamma, beta);

    // 2. Weight transposes + splits (K-major [N,K] operands)
    transpose_split_kernel<<<dim3(GH_ / 32, D_ / 32, 1), dim3(32, 8)>>>(gw1, pgw1hi, pgw1lo, D_, GH_);
    transpose_split_kernel<<<dim3(H_ / 32, D_ / 32, E_), dim3(32, 8)>>>(ew1, pw1hi, pw1lo, D_, H_);
    transpose_split_kernel<<<dim3(D_ / 32, H_ / 32, E_), dim3(32, 8)>>>(ew2, pw2hi, pw2lo, H_, D_);

    // 3. Gating layer1: g = gelu(h @ gw1 + gb1), fp32
    gemm_bf16x3<1><<<dim3(GH_ / 128, B_ / 128, 1), 256, SMEM_TC>>>(
        phhi, phlo, pgw1hi, pgw1lo, gb1,
        nullptr, nullptr, pg,
        D_, 0, 0, 0, 0, GH_, 0);

    // 4. Gate softmax + top-2
    gate_kernel<<<(B_ + 7) / 8, 256>>>(gw2, gb2, out);

    // 5. Expert GEMM1: hid[e] = gelu(h @ ew1[e] + eb1[e]), bf16 split out
    gemm_bf16x3<2><<<dim3(H_ / 128, B_ / 128, E_), 256, SMEM_TC>>>(
        phhi, phlo, pw1hi, pw1lo, eb1,
        phidhi, phidlo, nullptr,
        D_, 0, (size_t)H_ * D_, H_,
        (size_t)B_ * H_, H_, 0);

    // 6. Expert GEMM2: expert_outputs[:,e,:] = hid[e] @ ew2[e] + eb2[e] (fp32)
    gemm_bf16x3<0><<<dim3(D_ / 128, B_ / 128, E_), 256, SMEM_TC>>>(
        phidhi, phidlo, pw2hi, pw2lo, eb2,
        nullptr, nullptr, out + OFF_EO,
        H_, (size_t)B_ * H_, (size_t)D_ * H_, D_,
        0, E_ * D_, D_);

    // 7. Combine -> result
    combine_kernel<<<((int)((size_t)B_ * D_ + 255) / 256), 256>>>(out);
}

// round 6
// speedup vs baseline: 1.0611x; 1.0611x over previous
#include <cuda_runtime.h>
#include <cuda_bf16.h>
#include <math.h>
#include <stdint.h>

#define B_  8192
#define D_  768
#define GH_ 384
#define E_  8
#define H_  3072

#define OFF_GATE ((size_t)B_ * D_)
#define OFF_EO   (OFF_GATE + (size_t)B_ * E_)

__device__ float g_g[(size_t)B_ * GH_];
__device__ __align__(16) __nv_bfloat16 g_hhi[(size_t)B_ * D_];
__device__ __align__(16) __nv_bfloat16 g_hlo[(size_t)B_ * D_];
__device__ __align__(16) __nv_bfloat16 g_gw1hi[(size_t)GH_ * D_];
__device__ __align__(16) __nv_bfloat16 g_gw1lo[(size_t)GH_ * D_];
__device__ __align__(16) __nv_bfloat16 g_w1hi[(size_t)E_ * H_ * D_];
__device__ __align__(16) __nv_bfloat16 g_w1lo[(size_t)E_ * H_ * D_];
__device__ __align__(16) __nv_bfloat16 g_w2hi[(size_t)E_ * D_ * H_];
__device__ __align__(16) __nv_bfloat16 g_w2lo[(size_t)E_ * D_ * H_];
__device__ __align__(16) __nv_bfloat16 g_hidhi[(size_t)E_ * B_ * H_];
__device__ __align__(16) __nv_bfloat16 g_hidlo[(size_t)E_ * B_ * H_];
__device__ float g_tw[B_ * 2];
__device__ int   g_ti[B_ * 2];

__device__ __forceinline__ uint32_t smem_to_u32(const void* p) {
    uint32_t a;
    asm("{ .reg .u64 t; cvta.to.shared.u64 t, %1; cvt.u32.u64 %0, t; }" : "=r"(a) : "l"(p));
    return a;
}
__device__ __forceinline__ float geluf(float x) {
    return 0.5f * x * (1.f + erff(x * 0.7071067811865475f));
}
__device__ __forceinline__ void splitbf(float v, __nv_bfloat16& h, __nv_bfloat16& l) {
    h = __float2bfloat16(v);
    l = __float2bfloat16(v - __bfloat162float(h));
}
__device__ __forceinline__ uint32_t pack2(__nv_bfloat16 a, __nv_bfloat16 b) {
    return (uint32_t)__bfloat16_as_ushort(a) | ((uint32_t)__bfloat16_as_ushort(b) << 16);
}
__device__ __forceinline__ void cpa16(uint32_t dst, const void* src) {
    asm volatile("cp.async.cg.shared.global [%0], [%1], 16;" :: "r"(dst), "l"(src));
}
#define CP_COMMIT() asm volatile("cp.async.commit_group;" ::: "memory")
#define CP_WAIT1()  asm volatile("cp.async.wait_group 1;" ::: "memory")
#define CP_WAIT0()  asm volatile("cp.async.wait_group 0;" ::: "memory")

#define LDSM4(r, addr)                                                          \
    asm volatile("ldmatrix.sync.aligned.m8n8.x4.shared.b16 {%0,%1,%2,%3}, [%4];"\
                 : "=r"((r)[0]), "=r"((r)[1]), "=r"((r)[2]), "=r"((r)[3])       \
                 : "r"(addr))

#define MMA_BF16(d, a, b0, b1)                                                  \
    asm volatile("mma.sync.aligned.m16n8k16.row.col.f32.bf16.bf16.f32 "         \
                 "{%0,%1,%2,%3}, {%4,%5,%6,%7}, {%8,%9}, {%0,%1,%2,%3};"        \
                 : "+f"((d)[0]), "+f"((d)[1]), "+f"((d)[2]), "+f"((d)[3])       \
                 : "r"((a)[0]), "r"((a)[1]), "r"((a)[2]), "r"((a)[3]),          \
                   "r"(b0), "r"(b1))

// ---------------------------------------------------------------------------
__global__ void ln_kernel(const float* __restrict__ x,
                          const float* __restrict__ gamma,
                          const float* __restrict__ beta) {
    int b = blockIdx.x;
    const float* row = x + (size_t)b * D_;
    float s = 0.f, s2 = 0.f;
    for (int i = threadIdx.x; i < D_; i += blockDim.x) {
        float v = row[i];
        s += v; s2 += v * v;
    }
    __shared__ float red[64];
    for (int o = 16; o; o >>= 1) {
        s  += __shfl_down_sync(0xffffffffu, s,  o);
        s2 += __shfl_down_sync(0xffffffffu, s2, o);
    }
    int wid = threadIdx.x >> 5, lid = threadIdx.x & 31;
    if (lid == 0) { red[wid] = s; red[wid + 32] = s2; }
    __syncthreads();
    int nw = blockDim.x >> 5;
    if (wid == 0) {
        s  = (lid < nw) ? red[lid]      : 0.f;
        s2 = (lid < nw) ? red[lid + 32] : 0.f;
        for (int o = 16; o; o >>= 1) {
            s  += __shfl_down_sync(0xffffffffu, s,  o);
            s2 += __shfl_down_sync(0xffffffffu, s2, o);
        }
        if (lid == 0) { red[0] = s; red[1] = s2; }
    }
    __syncthreads();
    float mu   = red[0] / D_;
    float var  = red[1] / D_ - mu * mu;
    float rstd = rsqrtf(var + 1e-5f);
    for (int i = threadIdx.x; i < D_; i += blockDim.x) {
        float v = (row[i] - mu) * rstd * gamma[i] + beta[i];
        size_t idx = (size_t)b * D_ + i;
        __nv_bfloat16 hi, lo;
        splitbf(v, hi, lo);
        g_hhi[idx] = hi;
        g_hlo[idx] = lo;
    }
}

// ---------------------------------------------------------------------------
__global__ void transpose_split_kernel(const float* __restrict__ src,
                                       __nv_bfloat16* __restrict__ dhi,
                                       __nv_bfloat16* __restrict__ dlo,
                                       int R, int C) {
    __shared__ float t[32][33];
    int e = blockIdx.z;
    int c0 = blockIdx.x * 32, r0 = blockIdx.y * 32;
    const float* s = src + (size_t)e * R * C;
    #pragma unroll
    for (int i = 0; i < 32; i += 8)
        t[threadIdx.y + i][threadIdx.x] =
            s[(size_t)(r0 + threadIdx.y + i) * C + c0 + threadIdx.x];
    __syncthreads();
    size_t ob = (size_t)e * C * R;
    #pragma unroll
    for (int i = 0; i < 32; i += 8) {
        float v = t[threadIdx.x][threadIdx.y + i];
        __nv_bfloat16 hi, lo;
        splitbf(v, hi, lo);
        size_t o = ob + (size_t)(c0 + threadIdx.y + i) * R + r0 + threadIdx.x;
        dhi[o] = hi;
        dlo[o] = lo;
    }
}

// ---------------------------------------------------------------------------
// bf16x3 GEMM: 256x128x32 CTA tile, 8 warps of 64x64 (4x2 warp grid).
// Halved per-MAC smem traffic vs 128x128 (A read 2x redundant, not 4x).
// B fragments consumed in two N-halves per k-step to bound live registers.
// OUT_MODE: 0 = fp32 +bias, 1 = fp32 gelu, 2 = gelu + bf16 hi/lo split
// ---------------------------------------------------------------------------
#define BMT 256
#define BNT 128
#define BKC 32
#define A_REG 20480                    // 256 rows * 80B pitch
#define B_REG 10240                    // 128 rows * 80B pitch
#define STAGE_B (2 * A_REG + 2 * B_REG)   // 61440
#define NSTG 3
#define SMEM_TC (NSTG * STAGE_B)          // 184320

template <int OUT_MODE>
__global__ void __launch_bounds__(256) gemm_bf16x3(
    const __nv_bfloat16* __restrict__ Ahi, const __nv_bfloat16* __restrict__ Alo,
    const __nv_bfloat16* __restrict__ Bhi, const __nv_bfloat16* __restrict__ Blo,
    const float* __restrict__ bias,
    __nv_bfloat16* __restrict__ OutHi, __nv_bfloat16* __restrict__ OutLo,
    float* __restrict__ OutF,
    int Ktot, size_t aStrideE, size_t bStrideE, size_t biasStrideE,
    size_t cStrideE, int ldc, int cColStride)
{
    extern __shared__ char smem[];
    uint32_t sbase = smem_to_u32(smem);
    int tid  = threadIdx.x;
    int warp = tid >> 5, lane = tid & 31;
    int e  = blockIdx.z;
    int bm = blockIdx.y * BMT;
    int bn = blockIdx.x * BNT;
    int wm = (warp >> 1) * 64;          // 4 warps along M
    int wn = (warp & 1)  * 64;          // 2 warps along N
    int g  = lane >> 2, tg = lane & 3;

    const __nv_bfloat16* pAhi = Ahi + (size_t)e * aStrideE + (size_t)bm * Ktot;
    const __nv_bfloat16* pAlo = Alo + (size_t)e * aStrideE + (size_t)bm * Ktot;
    const __nv_bfloat16* pBhi = Bhi + (size_t)e * bStrideE + (size_t)bn * Ktot;
    const __nv_bfloat16* pBlo = Blo + (size_t)e * bStrideE + (size_t)bn * Ktot;

    int mi = lane >> 3, rr = lane & 7;
    uint32_t a_addr = sbase
        + (uint32_t)(wm + (mi & 1) * 8 + rr) * 80 + (uint32_t)(mi >> 1) * 16;
    uint32_t b_addr = sbase + 2u * A_REG
        + (uint32_t)(wn + (mi >> 1) * 8 + rr) * 80 + (uint32_t)(mi & 1) * 16;

    float acc[4][8][4];
    #pragma unroll
    for (int i = 0; i < 4; i++)
        #pragma unroll
        for (int j = 0; j < 8; j++)
            #pragma unroll
            for (int r = 0; r < 4; r++) acc[i][j][r] = 0.f;

    const int NC = Ktot / BKC;

    auto load_chunk = [&](int c, int st) {
        int k0 = c * BKC;
        uint32_t sb = sbase + (uint32_t)st * STAGE_B;
        #pragma unroll
        for (int i = 0; i < 4; i++) {           // A: 1024 16B-chunks
            int p = tid + i * 256;
            int row = p >> 2, col = p & 3;
            uint32_t d = sb + (uint32_t)row * 80 + (uint32_t)col * 16;
            size_t go = (size_t)row * Ktot + k0 + col * 8;
            cpa16(d,          pAhi + go);
            cpa16(d + A_REG,  pAlo + go);
        }
        #pragma unroll
        for (int i = 0; i < 2; i++) {           // B: 512 16B-chunks
            int p = tid + i * 256;
            int row = p >> 2, col = p & 3;
            uint32_t d = sb + 2u * A_REG + (uint32_t)row * 80 + (uint32_t)col * 16;
            size_t go = (size_t)row * Ktot + k0 + col * 8;
            cpa16(d,          pBhi + go);
            cpa16(d + B_REG,  pBlo + go);
        }
        CP_COMMIT();
    };

    load_chunk(0, 0);
    if (NC > 1) load_chunk(1, 1);

    for (int c = 0; c < NC; c++) {
        if (c + 1 < NC) { CP_WAIT1(); } else { CP_WAIT0(); }
        __syncthreads();
        if (c + 2 < NC) load_chunk(c + 2, (c + 2) % NSTG);

        uint32_t stoff = (uint32_t)((c % NSTG) * STAGE_B);
        #pragma unroll
        for (int ks = 0; ks < 2; ks++) {
            uint32_t ah[4][4], al[4][4];
            #pragma unroll
            for (int i = 0; i < 4; i++) {
                uint32_t ad = a_addr + stoff + (uint32_t)i * 1280 + (uint32_t)ks * 32;
                LDSM4(ah[i], ad);
                LDSM4(al[i], ad + A_REG);
            }
            #pragma unroll
            for (int jh = 0; jh < 2; jh++) {     // two N-halves: bound live regs
                uint32_t bh[2][4], bl[2][4];
                #pragma unroll
                for (int jp = 0; jp < 2; jp++) {
                    uint32_t bd = b_addr + stoff
                        + (uint32_t)(jh * 2 + jp) * 1280 + (uint32_t)ks * 32;
                    LDSM4(bh[jp], bd);
                    LDSM4(bl[jp], bd + B_REG);
                }
                #pragma unroll
                for (int i = 0; i < 4; i++)
                    #pragma unroll
                    for (int jl = 0; jl < 4; jl++) {
                        int j = jh * 4 + jl, jp = jl >> 1, hf = (jl & 1) * 2;
                        MMA_BF16(acc[i][j], ah[i], bh[jp][hf], bh[jp][hf + 1]);
                    }
                #pragma unroll
                for (int i = 0; i < 4; i++)
                    #pragma unroll
                    for (int jl = 0; jl < 4; jl++) {
                        int j = jh * 4 + jl, jp = jl >> 1, hf = (jl & 1) * 2;
                        MMA_BF16(acc[i][j], ah[i], bl[jp][hf], bl[jp][hf + 1]);
                    }
                #pragma unroll
                for (int i = 0; i < 4; i++)
                    #pragma unroll
                    for (int jl = 0; jl < 4; jl++) {
                        int j = jh * 4 + jl, jp = jl >> 1, hf = (jl & 1) * 2;
                        MMA_BF16(acc[i][j], al[i], bh[jp][hf], bh[jp][hf + 1]);
                    }
            }
        }
    }

    const float* bp = bias + (size_t)e * biasStrideE;
    #pragma unroll
    for (int i = 0; i < 4; i++) {
        int r0 = bm + wm + i * 16 + g;
        #pragma unroll
        for (int j = 0; j < 8; j++) {
            int c0 = bn + wn + j * 8 + tg * 2;
            float bi0 = bp[c0], bi1 = bp[c0 + 1];
            float v0 = acc[i][j][0] + bi0, v1 = acc[i][j][1] + bi1;
            float v2 = acc[i][j][2] + bi0, v3 = acc[i][j][3] + bi1;
            size_t rbA = (size_t)e * cStrideE + (size_t)r0 * ldc
                       + (size_t)e * cColStride + c0;
            size_t rbB = rbA + (size_t)8 * ldc;
            if (OUT_MODE == 0) {
                OutF[rbA] = v0; OutF[rbA + 1] = v1;
                OutF[rbB] = v2; OutF[rbB + 1] = v3;
            } else if (OUT_MODE == 1) {
                OutF[rbA] = geluf(v0); OutF[rbA + 1] = geluf(v1);
                OutF[rbB] = geluf(v2); OutF[rbB + 1] = geluf(v3);
            } else {
                v0 = geluf(v0); v1 = geluf(v1); v2 = geluf(v2); v3 = geluf(v3);
                __nv_bfloat16 h0, l0, h1, l1;
                splitbf(v0, h0, l0); splitbf(v1, h1, l1);
                *(uint32_t*)(OutHi + rbA) = pack2(h0, h1);
                *(uint32_t*)(OutLo + rbA) = pack2(l0, l1);
                splitbf(v2, h0, l0); splitbf(v3, h1, l1);
                *(uint32_t*)(OutHi + rbB) = pack2(h0, h1);
                *(uint32_t*)(OutLo + rbB) = pack2(l0, l1);
            }
        }
    }
}

// ---------------------------------------------------------------------------
__global__ void gate_kernel(const float* __restrict__ gw2,
                            const float* __restrict__ gb2,
                            float* __restrict__ dout) {
    int b = blockIdx.x * (blockDim.x >> 5) + (threadIdx.x >> 5);
    if (b >= B_) return;
    int lane = threadIdx.x & 31;
    int e = lane & 7, s = lane >> 3;

    const float* gr = g_g + (size_t)b * GH_;
    float acc = 0.f;
    int k0 = s * (GH_ / 4);
    #pragma unroll 4
    for (int k = k0; k < k0 + GH_ / 4; k++)
        acc = fmaf(gr[k], gw2[k * E_ + e], acc);
    acc += __shfl_xor_sync(0xffffffffu, acc, 8);
    acc += __shfl_xor_sync(0xffffffffu, acc, 16);
    float logit = acc + gb2[e];

    float m = logit;
    for (int o = 4; o; o >>= 1) m = fmaxf(m, __shfl_xor_sync(0xffffffffu, m, o));
    float p = (lane < E_) ? expf(logit - m) : 0.f;
    float ssum = p;
    for (int o = 16; o; o >>= 1) ssum += __shfl_xor_sync(0xffffffffu, ssum, o);
    float prob = p / ssum;
    if (lane < E_) dout[OFF_GATE + (size_t)b * E_ + lane] = prob;

    float v1 = (lane < E_) ? prob : -1.f; int i1 = lane;
    for (int o = 16; o; o >>= 1) {
        float ov = __shfl_xor_sync(0xffffffffu, v1, o);
        int   oi = __shfl_xor_sync(0xffffffffu, i1, o);
        if (ov > v1 || (ov == v1 && oi < i1)) { v1 = ov; i1 = oi; }
    }
    float v2 = (lane < E_ && lane != i1) ? prob : -1.f; int i2 = lane;
    for (int o = 16; o; o >>= 1) {
        float ov = __shfl_xor_sync(0xffffffffu, v2, o);
        int   oi = __shfl_xor_sync(0xffffffffu, i2, o);
        if (ov > v2 || (ov == v2 && oi < i2)) { v2 = ov; i2 = oi; }
    }
    if (lane == 0) {
        float sw = v1 + v2;
        g_tw[b * 2 + 0] = v1 / sw;
        g_tw[b * 2 + 1] = v2 / sw;
        g_ti[b * 2 + 0] = i1;
        g_ti[b * 2 + 1] = i2;
    }
}

// ---------------------------------------------------------------------------
__global__ void combine_kernel(float* __restrict__ dout) {
    size_t i = (size_t)blockIdx.x * blockDim.x + threadIdx.x;
    if (i >= (size_t)B_ * D_) return;
    int b = (int)(i / D_), d = (int)(i % D_);
    int   i0 = g_ti[b * 2], i1 = g_ti[b * 2 + 1];
    float w0 = g_tw[b * 2], w1 = g_tw[b * 2 + 1];
    const float* eo = dout + OFF_EO + (size_t)b * E_ * D_;
    dout[i] = w0 * eo[(size_t)i0 * D_ + d] + w1 * eo[(size_t)i1 * D_ + d];
}

// ---------------------------------------------------------------------------
extern "C" void kernel_launch(void* const* d_in, const int* in_sizes, int n_in,
                              void* d_out, int out_size) {
    const float* x     = (const float*)d_in[0];
    const float* gamma = (const float*)d_in[1];
    const float* beta  = (const float*)d_in[2];
    const float* gw1   = (const float*)d_in[3];
    const float* gb1   = (const float*)d_in[4];
    const float* gw2   = (const float*)d_in[5];
    const float* gb2   = (const float*)d_in[6];
    const float* ew1   = (const float*)d_in[7];
    const float* eb1   = (const float*)d_in[8];
    const float* ew2   = (const float*)d_in[9];
    const float* eb2   = (const float*)d_in[10];
    float* out = (float*)d_out;

    float *pg;
    __nv_bfloat16 *phhi, *phlo, *pgw1hi, *pgw1lo, *pw1hi, *pw1lo, *pw2hi, *pw2lo,
                  *phidhi, *phidlo;
    cudaGetSymbolAddress((void**)&pg,     g_g);
    cudaGetSymbolAddress((void**)&phhi,   g_hhi);
    cudaGetSymbolAddress((void**)&phlo,   g_hlo);
    cudaGetSymbolAddress((void**)&pgw1hi, g_gw1hi);
    cudaGetSymbolAddress((void**)&pgw1lo, g_gw1lo);
    cudaGetSymbolAddress((void**)&pw1hi,  g_w1hi);
    cudaGetSymbolAddress((void**)&pw1lo,  g_w1lo);
    cudaGetSymbolAddress((void**)&pw2hi,  g_w2hi);
    cudaGetSymbolAddress((void**)&pw2lo,  g_w2lo);
    cudaGetSymbolAddress((void**)&phidhi, g_hidhi);
    cudaGetSymbolAddress((void**)&phidlo, g_hidlo);

    cudaFuncSetAttribute(gemm_bf16x3<0>, cudaFuncAttributeMaxDynamicSharedMemorySize, SMEM_TC);
    cudaFuncSetAttribute(gemm_bf16x3<1>, cudaFuncAttributeMaxDynamicSharedMemorySize, SMEM_TC);
    cudaFuncSetAttribute(gemm_bf16x3<2>, cudaFuncAttributeMaxDynamicSharedMemorySize, SMEM_TC);

    // Launch order puts the two expert GEMMs at indices 5-6 so ncu -s 5 -c 1
    // captures a GEMM instead of a transpose.
    // 1. LayerNorm + bf16 split
    ln_kernel<<<B_, 256>>>(x, gamma, beta);

    // 2-4. Weight transposes + splits (K-major [N,K] operands)
    transpose_split_kernel<<<dim3(H_ / 32, D_ / 32, E_), dim3(32, 8)>>>(ew1, pw1hi, pw1lo, D_, H_);
    transpose_split_kernel<<<dim3(D_ / 32, H_ / 32, E_), dim3(32, 8)>>>(ew2, pw2hi, pw2lo, H_, D_);
    transpose_split_kernel<<<dim3(GH_ / 32, D_ / 32, 1), dim3(32, 8)>>>(gw1, pgw1hi, pgw1lo, D_, GH_);

    // 5. Expert GEMM1: hid[e] = gelu(h @ ew1[e] + eb1[e]), bf16 split out
    gemm_bf16x3<2><<<dim3(H_ / BNT, B_ / BMT, E_), 256, SMEM_TC>>>(
        phhi, phlo, pw1hi, pw1lo, eb1,
        phidhi, phidlo, nullptr,
        D_, 0, (size_t)H_ * D_, H_,
        (size_t)B_ * H_, H_, 0);

    // 6. Expert GEMM2: expert_outputs[:,e,:] = hid[e] @ ew2[e] + eb2[e] (fp32)
    gemm_bf16x3<0><<<dim3(D_ / BNT, B_ / BMT, E_), 256, SMEM_TC>>>(
        phidhi, phidlo, pw2hi, pw2lo, eb2,
        nullptr, nullptr, out + OFF_EO,
        H_, (size_t)B_ * H_, (size_t)D_ * H_, D_,
        0, E_ * D_, D_);

    // 7. Gating layer1: g = gelu(h @ gw1 + gb1), fp32
    gemm_bf16x3<1><<<dim3(GH_ / BNT, B_ / BMT, 1), 256, SMEM_TC>>>(
        phhi, phlo, pgw1hi, pgw1lo, gb1,
        nullptr, nullptr, pg,
        D_, 0, 0, 0, 0, GH_, 0);

    // 8. Gate softmax + top-2
    gate_kernel<<<(B_ + 7) / 8, 256>>>(gw2, gb2, out);

    // 9. Combine -> result
    combine_kernel<<<((int)((size_t)B_ * D_ + 255) / 256), 256>>>(out);
}